// round 14
// baseline (speedup 1.0000x reference)
#include <cuda_runtime.h>
#include <stdint.h>

// Shapes (fixed):
//   lstm : [4, 256, 128] f32   (512 KiB -> L1/L2 resident)
//   slic : [4, 512, 512] i32   (4 MiB, read once)
//   out  : [4, 512, 512, 128] f32 (512 MiB written -> the binding stream)
//
// R11: restore the proven winner (P=4 pixels/warp, 256-thread blocks,
// warp-uniform int4 id load, v4 gathers, __stcs streaming stores — R10
// proved __stcs is worth ~9%) and make the grid persistent: 1184 blocks
// (148 SMs x 8 CTAs) with a grid-stride loop over pixel groups. Removes
// ~27 waves of CTA launch/drain churn; loop iterations are independent so
// memory from iteration i+1 overlaps iteration i's store drain.

namespace {
constexpr int S = 256;
constexpr int C = 128;                 // floats per pixel row
constexpr int HW_SHIFT = 18;           // 512*512 = 1<<18
constexpr long long NPIX = 4LL << HW_SHIFT;        // 1,048,576
constexpr int PIX_PER_WARP = 4;
constexpr int WARPS_PER_BLOCK = 8;     // 256 threads
constexpr int THREADS = WARPS_PER_BLOCK * 32;
constexpr long long NGROUPS = NPIX / PIX_PER_WARP; // 262,144 warp-groups
constexpr int GRID = 148 * 8;          // persistent: 8 CTAs per SM
}

__global__ __launch_bounds__(THREADS)
void convert2image_gather4p(const float* __restrict__ lstm,
                            const int*   __restrict__ slic,
                            float*       __restrict__ out)
{
    const int lane = threadIdx.x & 31;
    const int warp = threadIdx.x >> 5;

    // Total warps in grid; each warp strides over pixel groups of 4.
    const long long warp_stride = (long long)gridDim.x * WARPS_PER_BLOCK;
    long long g = (long long)blockIdx.x * WARPS_PER_BLOCK + warp;

    for (; g < NGROUPS; g += warp_stride) {
        const long long p0 = g * PIX_PER_WARP;

        // Group shares one batch (p0 % 4 == 0, HW % 4 == 0).
        const int b = (int)(p0 >> HW_SHIFT);
        const float* __restrict__ lstm_b = lstm + (long long)b * S * C;

        // 1) One warp-uniform int4 load covers all 4 segment ids.
        const int4 s = __ldg(reinterpret_cast<const int4*>(slic + p0));
        const int seg[PIX_PER_WARP] = { s.x - 1, s.y - 1, s.z - 1, s.w - 1 };

        // 2) Four independent gather loads (lstm rows are L1 hits when warm).
        float4 v[PIX_PER_WARP];
#pragma unroll
        for (int i = 0; i < PIX_PER_WARP; ++i) {
            const float4* src =
                reinterpret_cast<const float4*>(lstm_b + (long long)seg[i] * C);
            v[i] = __ldg(&src[lane]);
        }

        // 3) Four independent streaming stores: warp writes 2 KB contiguous.
        float4* __restrict__ dst =
            reinterpret_cast<float4*>(out + p0 * (long long)C);
#pragma unroll
        for (int i = 0; i < PIX_PER_WARP; ++i)
            __stcs(&dst[i * 32 + lane], v[i]);
    }
}

extern "C" void kernel_launch(void* const* d_in, const int* in_sizes, int n_in,
                              void* d_out, int out_size)
{
    const float* lstm = (const float*)d_in[0];
    const int*   slic = (const int*)d_in[1];
    float*       out  = (float*)d_out;

    (void)in_sizes; (void)n_in; (void)out_size;

    convert2image_gather4p<<<GRID, THREADS>>>(lstm, slic, out);
}

// round 15
// speedup vs baseline: 1.0199x; 1.0199x over previous
#include <cuda_runtime.h>
#include <stdint.h>

// Shapes (fixed):
//   lstm : [4, 256, 128] f32   (512 KiB -> L1/L2 resident)
//   slic : [4, 512, 512] i32   (4 MiB, read once)
//   out  : [4, 512, 512, 128] f32 (512 MiB written -> the binding stream)
//
// R15: winner structure (P=4 pixels/warp, 256-thread blocks, warp-uniform
// int4 id load, v4 gathers) with WRITE-THROUGH stores (__stwt). Store policy
// is the proven high-leverage variable (cs beat default by 9%); wt is the
// extreme point of the "get writes out of L2 fast" axis. Persistent-grid
// (R14) and v8 (R9) experiments are rejected and fully reverted.

namespace {
constexpr int S = 256;
constexpr int C = 128;                 // floats per pixel row
constexpr int HW_SHIFT = 18;           // 512*512 = 1<<18
constexpr long long NPIX = 4LL << HW_SHIFT;   // 1,048,576
constexpr int PIX_PER_WARP = 4;
constexpr int WARPS_PER_BLOCK = 8;     // 256 threads (R6 winner)
constexpr int THREADS = WARPS_PER_BLOCK * 32;
constexpr int PIX_PER_BLOCK = WARPS_PER_BLOCK * PIX_PER_WARP;   // 32
}

__global__ __launch_bounds__(THREADS)
void convert2image_gather4wt(const float* __restrict__ lstm,
                             const int*   __restrict__ slic,
                             float*       __restrict__ out)
{
    const int lane = threadIdx.x & 31;
    const int warp = threadIdx.x >> 5;

    // First pixel of this warp's group of 4 (consecutive, 16B-aligned ids).
    const long long p0 = ((long long)blockIdx.x * WARPS_PER_BLOCK + warp)
                         * PIX_PER_WARP;

    // Group shares one batch (p0 % 4 == 0, HW % 4 == 0).
    const int b = (int)(p0 >> HW_SHIFT);
    const float* __restrict__ lstm_b = lstm + (long long)b * S * C;

    // 1) One warp-uniform int4 load covers all 4 segment ids.
    const int4 s = __ldg(reinterpret_cast<const int4*>(slic + p0));
    const int seg[PIX_PER_WARP] = { s.x - 1, s.y - 1, s.z - 1, s.w - 1 };

    // 2) Four independent gather loads (lstm rows are L1 hits when warm).
    float4 v[PIX_PER_WARP];
#pragma unroll
    for (int i = 0; i < PIX_PER_WARP; ++i) {
        const float4* src =
            reinterpret_cast<const float4*>(lstm_b + (long long)seg[i] * C);
        v[i] = __ldg(&src[lane]);
    }

    // 3) Four independent WRITE-THROUGH stores: warp writes 2 KB contiguous;
    //    lines stream toward DRAM without lingering dirty in L2.
    float4* __restrict__ dst =
        reinterpret_cast<float4*>(out + p0 * (long long)C);
#pragma unroll
    for (int i = 0; i < PIX_PER_WARP; ++i)
        __stwt(&dst[i * 32 + lane], v[i]);
}

extern "C" void kernel_launch(void* const* d_in, const int* in_sizes, int n_in,
                              void* d_out, int out_size)
{
    const float* lstm = (const float*)d_in[0];
    const int*   slic = (const int*)d_in[1];
    float*       out  = (float*)d_out;

    (void)in_sizes; (void)n_in; (void)out_size;

    const int grid = (int)(NPIX / PIX_PER_BLOCK);   // 32768, exact
    convert2image_gather4wt<<<grid, THREADS>>>(lstm, slic, out);
}